// round 3
// baseline (speedup 1.0000x reference)
#include <cuda_runtime.h>
#include <stdint.h>
#include <math.h>

// Problem constants (B=2, S=2048, H=2048, NH=16, HD=128)
namespace {
constexpr int Bc  = 2;
constexpr int Sc  = 2048;
constexpr int Hc  = 2048;
constexpr int NHc = 16;
constexpr int HDc = 128;
constexpr int BHc = Bc * NHc;                       // 32 batch-heads
constexpr float INV_NORM = 0.08838834764831845f;    // 1/sqrt(128)
constexpr float NEGF = -3.402823466385288598e38f;   // finfo(f32).min
}

// Scratch (device globals: allocation-free per harness rules)
__device__ float g_q[(size_t)BHc * Sc * HDc];           // [B,NH,S,HD], pre-scaled by 1/sqrt(HD)
__device__ float g_k[(size_t)BHc * Sc * HDc];
__device__ float g_v[(size_t)BHc * Sc * HDc];
__device__ float g_ctx[(size_t)Bc * Sc * Hc];           // [B,S,H]
__device__ float g_p[(size_t)BHc * Sc * Sc];            // scores/probs [B*NH,S,S] (512 MB)

// ---------------------------------------------------------------------------
// One tiled SGEMM, 4 modes:
//  MODE 0: fused = hs @ w_qkv^T + b_qkv, scatter into g_q (*inv_norm), g_k, g_v
//  MODE 1: scores = (q @ k^T) + alibi, masked -> NEG  (batched over z = b*NH+h)
//  MODE 2: ctx = probs @ v (NN gemm, batched), scatter into g_ctx [B,S,H]
//  MODE 3: out = ctx @ w_dense^T + b_dense + residual
// 128x128 block tile, BK=8, 8x8 per thread, 256 threads.
// ---------------------------------------------------------------------------
template<int MODE>
__global__ __launch_bounds__(256, 2)
void gemm_kernel(const float* __restrict__ Ain, const float* __restrict__ Bin,
                 const float* __restrict__ bias, const int* __restrict__ mask,
                 const float* __restrict__ alibi, const float* __restrict__ residual,
                 float* __restrict__ Cout, int M, int N, int K)
{
    const int z = blockIdx.z;
    const float* A;
    const float* Bm;
    if constexpr (MODE == 0)      { A = Ain;                          Bm = Bin; }
    else if constexpr (MODE == 1) { A = g_q + (size_t)z * Sc * HDc;   Bm = g_k + (size_t)z * Sc * HDc; }
    else if constexpr (MODE == 2) { A = g_p + (size_t)z * Sc * Sc;    Bm = g_v + (size_t)z * Sc * HDc; }
    else                          { A = g_ctx;                        Bm = Bin; }

    __shared__ float As[8][128];
    __shared__ float Bs[8][128];

    const int tid = threadIdx.x;
    const int tx = tid & 15;       // 16 thread cols
    const int ty = tid >> 4;       // 16 thread rows
    const int m0 = blockIdx.y * 128;
    const int n0 = blockIdx.x * 128;

    float acc[8][8];
    #pragma unroll
    for (int i = 0; i < 8; ++i)
        #pragma unroll
        for (int j = 0; j < 8; ++j) acc[i][j] = 0.f;

    const int arow = tid >> 1;          // 0..127
    const int acol = (tid & 1) * 4;     // 0 or 4

    for (int k0 = 0; k0 < K; k0 += 8) {
        // A tile: A is [M,K] row-major; store transposed As[k][m]
        {
            float4 av = *(const float4*)(A + (size_t)(m0 + arow) * K + (k0 + acol));
            As[acol + 0][arow] = av.x;
            As[acol + 1][arow] = av.y;
            As[acol + 2][arow] = av.z;
            As[acol + 3][arow] = av.w;
        }
        if constexpr (MODE == 2) {
            // NN: B is [K,N] row-major
            const int krow = tid >> 5;            // 0..7
            const int ncol = (tid & 31) * 4;      // 0..124
            float4 bv = *(const float4*)(Bm + (size_t)(k0 + krow) * N + (n0 + ncol));
            *(float4*)&Bs[krow][ncol] = bv;
        } else {
            // NT: B is [N,K] row-major; store transposed Bs[k][n]
            float4 bv = *(const float4*)(Bm + (size_t)(n0 + arow) * K + (k0 + acol));
            Bs[acol + 0][arow] = bv.x;
            Bs[acol + 1][arow] = bv.y;
            Bs[acol + 2][arow] = bv.z;
            Bs[acol + 3][arow] = bv.w;
        }
        __syncthreads();

        #pragma unroll
        for (int kk = 0; kk < 8; ++kk) {
            float a[8], b[8];
            *(float4*)&a[0] = *(const float4*)&As[kk][ty * 8];
            *(float4*)&a[4] = *(const float4*)&As[kk][ty * 8 + 4];
            *(float4*)&b[0] = *(const float4*)&Bs[kk][tx * 8];
            *(float4*)&b[4] = *(const float4*)&Bs[kk][tx * 8 + 4];
            #pragma unroll
            for (int i = 0; i < 8; ++i)
                #pragma unroll
                for (int j = 0; j < 8; ++j)
                    acc[i][j] = fmaf(a[i], b[j], acc[i][j]);
        }
        __syncthreads();
    }

    // Epilogue
    #pragma unroll
    for (int i = 0; i < 8; ++i) {
        const int m = m0 + ty * 8 + i;
        #pragma unroll
        for (int j = 0; j < 8; ++j) {
            const int n = n0 + tx * 8 + j;
            float v = acc[i][j];
            if constexpr (MODE == 0) {
                v += bias[n];
                const int b  = m / Sc;
                const int s  = m - b * Sc;
                const int nh = n / (3 * HDc);
                const int r  = n - nh * 3 * HDc;
                const int t  = r / HDc;
                const int d  = r - t * HDc;
                const size_t off = ((size_t)(b * NHc + nh) * Sc + s) * HDc + d;
                if (t == 0)      g_q[off] = v * INV_NORM;
                else if (t == 1) g_k[off] = v;
                else             g_v[off] = v;
            } else if constexpr (MODE == 1) {
                v += alibi[z * Sc + n];
                if (mask[(size_t)m * Sc + n] != 0) v = NEGF;
                g_p[(size_t)z * Sc * Sc + (size_t)m * Sc + n] = v;
            } else if constexpr (MODE == 2) {
                const int b  = z / NHc;
                const int nh = z - b * NHc;
                g_ctx[(size_t)(b * Sc + m) * Hc + nh * HDc + n] = v;
            } else {
                Cout[(size_t)m * Hc + n] = v + bias[n] + residual[(size_t)m * Hc + n];
            }
        }
    }
}

// ---------------------------------------------------------------------------
// Row softmax over g_p: one block per row of 2048, 256 threads x 8 elems.
// ---------------------------------------------------------------------------
__global__ __launch_bounds__(256)
void softmax_kernel()
{
    const size_t row = blockIdx.x;
    float* pr = g_p + row * (size_t)Sc;
    const int t = threadIdx.x;
    const int lane = t & 31, warp = t >> 5;
    __shared__ float red[8];

    float v[8];
    float mx = -INFINITY;
    #pragma unroll
    for (int i = 0; i < 8; ++i) { v[i] = pr[i * 256 + t]; mx = fmaxf(mx, v[i]); }
    #pragma unroll
    for (int o = 16; o > 0; o >>= 1) mx = fmaxf(mx, __shfl_xor_sync(0xffffffffu, mx, o));
    if (lane == 0) red[warp] = mx;
    __syncthreads();
    mx = red[0];
    #pragma unroll
    for (int w = 1; w < 8; ++w) mx = fmaxf(mx, red[w]);
    __syncthreads();   // everyone done reading red before reuse

    float sum = 0.f;
    #pragma unroll
    for (int i = 0; i < 8; ++i) { v[i] = expf(v[i] - mx); sum += v[i]; }
    #pragma unroll
    for (int o = 16; o > 0; o >>= 1) sum += __shfl_xor_sync(0xffffffffu, sum, o);
    if (lane == 0) red[warp] = sum;
    __syncthreads();
    float tot = red[0];
    #pragma unroll
    for (int w = 1; w < 8; ++w) tot += red[w];
    const float inv = 1.0f / tot;
    #pragma unroll
    for (int i = 0; i < 8; ++i) pr[i * 256 + t] = v[i] * inv;
}

// ---------------------------------------------------------------------------
// Inputs (metadata order): hidden_states, residual, alibi, attention_mask(bool->int32),
//                          w_qkv, b_qkv, w_dense, b_dense
// ---------------------------------------------------------------------------
extern "C" void kernel_launch(void* const* d_in, const int* in_sizes, int n_in,
                              void* d_out, int out_size)
{
    (void)in_sizes; (void)n_in; (void)out_size;
    const float* hs       = (const float*)d_in[0];
    const float* residual = (const float*)d_in[1];
    const float* alibi    = (const float*)d_in[2];
    const int*   mask     = (const int*)d_in[3];      // bool upcast to int32 by harness
    const float* w_qkv    = (const float*)d_in[4];
    const float* b_qkv    = (const float*)d_in[5];
    const float* w_dense  = (const float*)d_in[6];
    const float* b_dense  = (const float*)d_in[7];
    float*       out      = (float*)d_out;

    const dim3 blk(256);

    // 1) QKV projection + scatter:  M=4096, N=6144, K=2048
    gemm_kernel<0><<<dim3(6144 / 128, 4096 / 128, 1), blk>>>(
        hs, w_qkv, b_qkv, nullptr, nullptr, nullptr, nullptr, Bc * Sc, 3 * Hc, Hc);

    // 2) scores = q@k^T + alibi, mask:  per-bh M=N=2048, K=128
    gemm_kernel<1><<<dim3(Sc / 128, Sc / 128, BHc), blk>>>(
        nullptr, nullptr, nullptr, mask, alibi, nullptr, nullptr, Sc, Sc, HDc);

    // 3) row softmax over 2048-wide rows
    softmax_kernel<<<BHc * Sc, 256>>>();

    // 4) ctx = probs@v:  per-bh M=2048, N=128, K=2048
    gemm_kernel<2><<<dim3(HDc / 128, Sc / 128, BHc), blk>>>(
        nullptr, nullptr, nullptr, nullptr, nullptr, nullptr, nullptr, Sc, HDc, Sc);

    // 5) out = ctx@w_dense^T + b_dense + residual:  M=4096, N=2048, K=2048
    gemm_kernel<3><<<dim3(Hc / 128, (Bc * Sc) / 128, 1), blk>>>(
        nullptr, w_dense, b_dense, nullptr, nullptr, residual, out, Bc * Sc, Hc, Hc);
}

// round 4
// speedup vs baseline: 1.2208x; 1.2208x over previous
#include <cuda_runtime.h>
#include <mma.h>
#include <stdint.h>
#include <math.h>

using namespace nvcuda;

// Problem constants (B=2, S=2048, H=2048, NH=16, HD=128)
namespace {
constexpr int Bc  = 2;
constexpr int Sc  = 2048;
constexpr int Hc  = 2048;
constexpr int NHc = 16;
constexpr int HDc = 128;
constexpr int BHc = Bc * NHc;                       // 32 batch-heads
constexpr float INV_NORM = 0.08838834764831845f;    // 1/sqrt(128)
constexpr float NEGF = -3.402823466385288598e38f;   // finfo(f32).min

constexpr int BM = 128, BN = 128, BK = 32;
constexpr int APAD = 8;  // As ldm = BK+8 = 40
constexpr int BPAD = 8;  // Bs ldm = BN+8 = 136
}

// Scratch (device globals: allocation-free per harness rules)
__device__ float g_q[(size_t)BHc * Sc * HDc];           // [B,NH,S,HD], pre-scaled by 1/sqrt(HD)
__device__ float g_k[(size_t)BHc * Sc * HDc];
__device__ float g_v[(size_t)BHc * Sc * HDc];
__device__ float g_ctx[(size_t)Bc * Sc * Hc];           // [B,S,H]
__device__ float g_fused[(size_t)Bc * Sc * 3 * Hc];     // raw QKV GEMM out [4096, 6144]
__device__ float g_p[(size_t)BHc * Sc * Sc];            // scores/probs [B*NH,S,S] (512 MB)

// ---------------------------------------------------------------------------
// tf32 wmma GEMM. C = A @ op(B). Pure GEMM; per-element epilogues moved to
// separate passes. 128x128x32 tile, 8 warps (4x2), warp tile 32x64, m16n16k8.
//  MODE 0: g_fused = hs @ w_qkv^T           (NT)  M=4096 N=6144 K=2048
//  MODE 1: g_p[z]  = q[z] @ k[z]^T          (NT)  M=N=2048 K=128, batched z
//  MODE 2: g_ctx   = probs[z] @ v[z]        (NN)  M=2048 N=128 K=2048, batched
//  MODE 3: out     = g_ctx @ w_dense^T      (NT)  M=4096 N=2048 K=2048
// ---------------------------------------------------------------------------
template<int MODE>
__global__ __launch_bounds__(256)
void gemm_tf32(const float* __restrict__ Ag, const float* __restrict__ Bg,
               float* __restrict__ Cg)
{
    const int z = blockIdx.z;

    const float* A;  const float* Bm;  float* C;
    int lda, ldb, ldc, K;
    if constexpr (MODE == 0) {
        A = Ag;  lda = Hc;  Bm = Bg;  ldb = Hc;  K = Hc;
        C = g_fused;  ldc = 3 * Hc;
    } else if constexpr (MODE == 1) {
        A = g_q + (size_t)z * Sc * HDc;  lda = HDc;
        Bm = g_k + (size_t)z * Sc * HDc; ldb = HDc;  K = HDc;
        C = g_p + (size_t)z * Sc * Sc;   ldc = Sc;
    } else if constexpr (MODE == 2) {
        A = g_p + (size_t)z * Sc * Sc;   lda = Sc;
        Bm = g_v + (size_t)z * Sc * HDc; ldb = HDc;  K = Sc;
        const int b = z / NHc, nh = z - b * NHc;
        C = g_ctx + (size_t)(b * Sc) * Hc + nh * HDc;  ldc = Hc;
    } else {
        A = g_ctx;  lda = Hc;  Bm = Bg;  ldb = Hc;  K = Hc;
        C = Cg;  ldc = Hc;
    }

    __shared__ float As[BM][BK + APAD];   // [128][40]
    __shared__ float Bs[BK][BN + BPAD];   // [32][136]

    const int tid  = threadIdx.x;
    const int warp = tid >> 5;
    const int wm   = warp >> 1;   // 0..3 -> 32-row slice
    const int wn   = warp & 1;    // 0..1 -> 64-col slice
    const int m0   = blockIdx.y * BM;
    const int n0   = blockIdx.x * BN;

    wmma::fragment<wmma::accumulator, 16, 16, 8, float> c[2][4];
    #pragma unroll
    for (int i = 0; i < 2; ++i)
        #pragma unroll
        for (int j = 0; j < 4; ++j) wmma::fill_fragment(c[i][j], 0.0f);

    for (int k0 = 0; k0 < K; k0 += BK) {
        // --- A tile: [BM][BK] row-major copy (all modes A is [M,K] row-major)
        #pragma unroll
        for (int i = tid; i < BM * (BK / 4); i += 256) {       // 1024 float4
            const int row = i >> 3, c4 = (i & 7) * 4;
            float4 v = *(const float4*)(A + (size_t)(m0 + row) * lda + k0 + c4);
            *(float4*)&As[row][c4] = v;
        }
        // --- B tile into Bs[k][n]
        if constexpr (MODE == 2) {
            // NN: B is [K,N] row-major -> direct copy
            #pragma unroll
            for (int i = tid; i < BK * (BN / 4); i += 256) {   // 1024 float4
                const int k = i >> 5, n4 = (i & 31) * 4;
                float4 v = *(const float4*)(Bm + (size_t)(k0 + k) * ldb + n0 + n4);
                *(float4*)&Bs[k][n4] = v;
            }
        } else {
            // NT: B is [N,K] row-major -> transpose on store
            #pragma unroll
            for (int i = tid; i < BN * (BK / 4); i += 256) {   // 1024 float4
                const int n = i >> 3, k4 = (i & 7) * 4;
                float4 v = *(const float4*)(Bm + (size_t)(n0 + n) * ldb + k0 + k4);
                Bs[k4 + 0][n] = v.x;
                Bs[k4 + 1][n] = v.y;
                Bs[k4 + 2][n] = v.z;
                Bs[k4 + 3][n] = v.w;
            }
        }
        __syncthreads();

        #pragma unroll
        for (int kk = 0; kk < BK / 8; ++kk) {
            wmma::fragment<wmma::matrix_a, 16, 16, 8, wmma::precision::tf32, wmma::row_major> a[2];
            #pragma unroll
            for (int i = 0; i < 2; ++i) {
                wmma::load_matrix_sync(a[i], &As[wm * 32 + i * 16][kk * 8], BK + APAD);
                #pragma unroll
                for (int t = 0; t < a[i].num_elements; ++t)
                    a[i].x[t] = wmma::__float_to_tf32(a[i].x[t]);
            }
            #pragma unroll
            for (int j = 0; j < 4; ++j) {
                wmma::fragment<wmma::matrix_b, 16, 16, 8, wmma::precision::tf32, wmma::row_major> b;
                wmma::load_matrix_sync(b, &Bs[kk * 8][wn * 64 + j * 16], BN + BPAD);
                #pragma unroll
                for (int t = 0; t < b.num_elements; ++t)
                    b.x[t] = wmma::__float_to_tf32(b.x[t]);
                #pragma unroll
                for (int i = 0; i < 2; ++i)
                    wmma::mma_sync(c[i][j], a[i], b, c[i][j]);
            }
        }
        __syncthreads();
    }

    #pragma unroll
    for (int i = 0; i < 2; ++i)
        #pragma unroll
        for (int j = 0; j < 4; ++j)
            wmma::store_matrix_sync(
                C + (size_t)(m0 + wm * 32 + i * 16) * ldc + (n0 + wn * 64 + j * 16),
                c[i][j], ldc, wmma::mem_row_major);
}

// ---------------------------------------------------------------------------
// QKV scatter: g_fused [4096,6144] + bias -> g_q(*INV_NORM)/g_k/g_v [B,NH,S,HD]
// ---------------------------------------------------------------------------
__global__ __launch_bounds__(256)
void qkv_scatter(const float* __restrict__ bias)
{
    const size_t i4 = ((size_t)blockIdx.x * 256 + threadIdx.x) * 4;
    const int m = (int)(i4 / (3 * Hc));
    const int n = (int)(i4 % (3 * Hc));
    float4 v  = *(const float4*)&g_fused[i4];
    float4 bb = *(const float4*)&bias[n];
    v.x += bb.x; v.y += bb.y; v.z += bb.z; v.w += bb.w;

    const int nh = n / (3 * HDc);
    const int r  = n - nh * 3 * HDc;
    const int t  = r / HDc;
    const int d  = r - t * HDc;
    const int b  = m / Sc;
    const int s  = m - b * Sc;
    const size_t off = ((size_t)(b * NHc + nh) * Sc + s) * HDc + d;

    if (t == 0) {
        v.x *= INV_NORM; v.y *= INV_NORM; v.z *= INV_NORM; v.w *= INV_NORM;
        *(float4*)&g_q[off] = v;
    } else if (t == 1) {
        *(float4*)&g_k[off] = v;
    } else {
        *(float4*)&g_v[off] = v;
    }
}

// ---------------------------------------------------------------------------
// Fused alibi + mask + softmax over g_p rows (2048 wide).
// ---------------------------------------------------------------------------
__global__ __launch_bounds__(256)
void softmax_kernel(const float* __restrict__ alibi, const int* __restrict__ mask)
{
    const size_t row = blockIdx.x;
    const int z = (int)(row / Sc);
    const int m = (int)(row % Sc);
    float* pr = g_p + row * (size_t)Sc;
    const float* al = alibi + (size_t)z * Sc;
    const int* mr = mask + (size_t)m * Sc;

    const int t = threadIdx.x;
    const int lane = t & 31, warp = t >> 5;
    __shared__ float red[8];

    float v[8];
    float mx = -INFINITY;
    #pragma unroll
    for (int i = 0; i < 8; ++i) {
        const int col = i * 256 + t;
        float s = pr[col] + al[col];
        if (mr[col] != 0) s = NEGF;
        v[i] = s;
        mx = fmaxf(mx, s);
    }
    #pragma unroll
    for (int o = 16; o > 0; o >>= 1) mx = fmaxf(mx, __shfl_xor_sync(0xffffffffu, mx, o));
    if (lane == 0) red[warp] = mx;
    __syncthreads();
    mx = red[0];
    #pragma unroll
    for (int w = 1; w < 8; ++w) mx = fmaxf(mx, red[w]);
    __syncthreads();

    float sum = 0.f;
    #pragma unroll
    for (int i = 0; i < 8; ++i) { v[i] = expf(v[i] - mx); sum += v[i]; }
    #pragma unroll
    for (int o = 16; o > 0; o >>= 1) sum += __shfl_xor_sync(0xffffffffu, sum, o);
    if (lane == 0) red[warp] = sum;
    __syncthreads();
    float tot = red[0];
    #pragma unroll
    for (int w = 1; w < 8; ++w) tot += red[w];
    const float inv = 1.0f / tot;
    #pragma unroll
    for (int i = 0; i < 8; ++i) pr[i * 256 + t] = v[i] * inv;
}

// ---------------------------------------------------------------------------
// Dense epilogue fixup: out += b_dense[n] + residual
// ---------------------------------------------------------------------------
__global__ __launch_bounds__(256)
void dense_epilogue(float* __restrict__ out, const float* __restrict__ bias,
                    const float* __restrict__ residual)
{
    const size_t i4 = ((size_t)blockIdx.x * 256 + threadIdx.x) * 4;
    const int n = (int)(i4 % Hc);
    float4 v  = *(float4*)&out[i4];
    float4 bb = *(const float4*)&bias[n];
    float4 rr = *(const float4*)&residual[i4];
    v.x += bb.x + rr.x; v.y += bb.y + rr.y; v.z += bb.z + rr.z; v.w += bb.w + rr.w;
    *(float4*)&out[i4] = v;
}

// ---------------------------------------------------------------------------
// Inputs (metadata order): hidden_states, residual, alibi, attention_mask(int32),
//                          w_qkv, b_qkv, w_dense, b_dense
// ---------------------------------------------------------------------------
extern "C" void kernel_launch(void* const* d_in, const int* in_sizes, int n_in,
                              void* d_out, int out_size)
{
    (void)in_sizes; (void)n_in; (void)out_size;
    const float* hs       = (const float*)d_in[0];
    const float* residual = (const float*)d_in[1];
    const float* alibi    = (const float*)d_in[2];
    const int*   mask     = (const int*)d_in[3];      // bool upcast to int32 by harness
    const float* w_qkv    = (const float*)d_in[4];
    const float* b_qkv    = (const float*)d_in[5];
    const float* w_dense  = (const float*)d_in[6];
    const float* b_dense  = (const float*)d_in[7];
    float*       out      = (float*)d_out;

    const dim3 blk(256);

    // 1) raw QKV GEMM: g_fused = hs @ w_qkv^T   [4096, 6144]
    gemm_tf32<0><<<dim3((3 * Hc) / BN, (Bc * Sc) / BM, 1), blk>>>(hs, w_qkv, nullptr);

    // 2) scatter + bias + q-prescale
    qkv_scatter<<<(unsigned)((size_t)Bc * Sc * 3 * Hc / 4 / 256), blk>>>(b_qkv);

    // 3) raw scores: g_p[z] = q' @ k^T
    gemm_tf32<1><<<dim3(Sc / BN, Sc / BM, BHc), blk>>>(nullptr, nullptr, nullptr);

    // 4) alibi + mask + softmax
    softmax_kernel<<<BHc * Sc, 256>>>(alibi, mask);

    // 5) ctx: g_ctx = probs @ v   (scattered into [B,S,H])
    gemm_tf32<2><<<dim3(HDc / BN, Sc / BM, BHc), blk>>>(nullptr, nullptr, nullptr);

    // 6) out = ctx @ w_dense^T
    gemm_tf32<3><<<dim3(Hc / BN, (Bc * Sc) / BM, 1), blk>>>(nullptr, w_dense, out);

    // 7) out += b_dense + residual
    dense_epilogue<<<(unsigned)((size_t)Bc * Sc * Hc / 4 / 256), blk>>>(out, b_dense, residual);
}

// round 5
// speedup vs baseline: 1.7336x; 1.4200x over previous
#include <cuda_runtime.h>
#include <mma.h>
#include <stdint.h>
#include <math.h>

using namespace nvcuda;

// Problem constants (B=2, S=2048, H=2048, NH=16, HD=128)
namespace {
constexpr int Bc  = 2;
constexpr int Sc  = 2048;
constexpr int Hc  = 2048;
constexpr int NHc = 16;
constexpr int HDc = 128;
constexpr int BHc = Bc * NHc;                       // 32 batch-heads
constexpr float INV_NORM = 0.08838834764831845f;    // 1/sqrt(128)
constexpr float NEGF = -3.402823466385288598e38f;   // finfo(f32).min

constexpr int BM = 128, BN = 128, BK = 32;
constexpr int PAD  = 8;
constexpr int LDA  = BK + PAD;                      // 40
constexpr int LDBN = BN + PAD;                      // 136 (NN tiles)
constexpr int ASZ  = BM * LDA;                      // 5120 floats per stage
constexpr int BSZ  = 5120;                          // max(BN*LDA=5120, BK*LDBN=4352)
constexpr size_t SMEM_BYTES = (size_t)(2 * ASZ + 2 * BSZ) * 4;   // 81920
}

// Scratch (device globals: allocation-free per harness rules)
__device__ __align__(16) float g_q[(size_t)BHc * Sc * HDc];       // pre-scaled by 1/sqrt(HD)
__device__ __align__(16) float g_k[(size_t)BHc * Sc * HDc];
__device__ __align__(16) float g_v[(size_t)BHc * Sc * HDc];
__device__ __align__(16) float g_ctx[(size_t)Bc * Sc * Hc];       // [B,S,H]
__device__ __align__(16) float g_fused[(size_t)Bc * Sc * 3 * Hc]; // raw QKV out [4096,6144]
__device__ __align__(16) float g_p[(size_t)BHc * Sc * Sc];        // scores/probs (512 MB)

__device__ __forceinline__ void cp_async16(float* sptr, const float* gptr) {
    uint32_t saddr = (uint32_t)__cvta_generic_to_shared(sptr);
    asm volatile("cp.async.cg.shared.global [%0], [%1], 16;\n" :: "r"(saddr), "l"(gptr));
}
__device__ __forceinline__ void cp_commit() { asm volatile("cp.async.commit_group;\n"); }
template<int N>
__device__ __forceinline__ void cp_wait() { asm volatile("cp.async.wait_group %0;\n" :: "n"(N)); }

// ---------------------------------------------------------------------------
// tf32 wmma GEMM, cp.async double-buffered. C = A @ op(B).
//  MODE 0: g_fused = hs @ w_qkv^T      (NT)  M=4096 N=6144 K=2048
//  MODE 1: g_p[z]  = q[z] @ k[z]^T     (NT)  M=N=2048 K=128, batched z
//  MODE 2: g_ctx   = probs[z] @ v[z]   (NN)  M=2048 N=128 K=2048, batched
//  MODE 3: out     = g_ctx @ w_dense^T (NT)  M=4096 N=2048 K=2048
// NT B-tiles stored untransposed [BN][BK] -> wmma col_major fragments.
// 8 warps (4x2), warp tile 32x64, m16n16k8.
// ---------------------------------------------------------------------------
template<int MODE>
__global__ __launch_bounds__(256, 2)
void gemm_tf32(const float* __restrict__ Ag, const float* __restrict__ Bg,
               float* __restrict__ Cg)
{
    constexpr bool NT = (MODE != 2);
    const int z = blockIdx.z;

    const float* A;  const float* Bm;  float* C;
    int lda, ldb, ldc, K;
    if constexpr (MODE == 0) {
        A = Ag;  lda = Hc;  Bm = Bg;  ldb = Hc;  K = Hc;
        C = g_fused;  ldc = 3 * Hc;
    } else if constexpr (MODE == 1) {
        A = g_q + (size_t)z * Sc * HDc;  lda = HDc;
        Bm = g_k + (size_t)z * Sc * HDc; ldb = HDc;  K = HDc;
        C = g_p + (size_t)z * Sc * Sc;   ldc = Sc;
    } else if constexpr (MODE == 2) {
        A = g_p + (size_t)z * Sc * Sc;   lda = Sc;
        Bm = g_v + (size_t)z * Sc * HDc; ldb = HDc;  K = Sc;
        const int b = z / NHc, nh = z - b * NHc;
        C = g_ctx + (size_t)(b * Sc) * Hc + nh * HDc;  ldc = Hc;
    } else {
        A = g_ctx;  lda = Hc;  Bm = Bg;  ldb = Hc;  K = Hc;
        C = Cg;  ldc = Hc;
    }

    extern __shared__ float smem[];
    float* As = smem;                 // [2][BM][LDA]
    float* Bs = smem + 2 * ASZ;       // [2][BN][LDA] (NT) or [2][BK][LDBN] (NN)

    const int tid  = threadIdx.x;
    const int warp = tid >> 5;
    const int wm   = warp >> 1;       // 0..3 -> 32-row slice
    const int wn   = warp & 1;        // 0..1 -> 64-col slice
    const int m0   = blockIdx.y * BM;
    const int n0   = blockIdx.x * BN;

    // tile loaders: 1024 x 16B chunks each, 4 per thread
    auto load_A = [&](int st, int k0) {
        #pragma unroll
        for (int c = 0; c < 4; ++c) {
            const int idx = tid + c * 256;
            const int row = idx >> 3, col = (idx & 7) * 4;
            cp_async16(&As[st * ASZ + row * LDA + col],
                       A + (size_t)(m0 + row) * lda + (k0 + col));
        }
    };
    auto load_B = [&](int st, int k0) {
        if constexpr (NT) {
            #pragma unroll
            for (int c = 0; c < 4; ++c) {
                const int idx = tid + c * 256;
                const int row = idx >> 3, col = (idx & 7) * 4;   // row=n, col=k
                cp_async16(&Bs[st * BSZ + row * LDA + col],
                           Bm + (size_t)(n0 + row) * ldb + (k0 + col));
            }
        } else {
            #pragma unroll
            for (int c = 0; c < 4; ++c) {
                const int idx = tid + c * 256;
                const int k = idx >> 5, n4 = (idx & 31) * 4;
                cp_async16(&Bs[st * BSZ + k * LDBN + n4],
                           Bm + (size_t)(k0 + k) * ldb + (n0 + n4));
            }
        }
    };

    wmma::fragment<wmma::accumulator, 16, 16, 8, float> c[2][4];
    #pragma unroll
    for (int i = 0; i < 2; ++i)
        #pragma unroll
        for (int j = 0; j < 4; ++j) wmma::fill_fragment(c[i][j], 0.0f);

    load_A(0, 0); load_B(0, 0); cp_commit();

    for (int k0 = 0; k0 < K; k0 += BK) {
        const int cur = (k0 / BK) & 1;
        if (k0 + BK < K) {
            load_A(cur ^ 1, k0 + BK); load_B(cur ^ 1, k0 + BK);
            cp_commit();
            cp_wait<1>();
        } else {
            cp_wait<0>();
        }
        __syncthreads();

        const float* Ab = &As[cur * ASZ];
        const float* Bb = &Bs[cur * BSZ];
        #pragma unroll
        for (int kk = 0; kk < BK / 8; ++kk) {
            wmma::fragment<wmma::matrix_a, 16, 16, 8, wmma::precision::tf32, wmma::row_major> a[2];
            #pragma unroll
            for (int i = 0; i < 2; ++i) {
                wmma::load_matrix_sync(a[i], Ab + (wm * 32 + i * 16) * LDA + kk * 8, LDA);
                #pragma unroll
                for (int t = 0; t < a[i].num_elements; ++t)
                    a[i].x[t] = wmma::__float_to_tf32(a[i].x[t]);
            }
            #pragma unroll
            for (int j = 0; j < 4; ++j) {
                if constexpr (NT) {
                    wmma::fragment<wmma::matrix_b, 16, 16, 8, wmma::precision::tf32, wmma::col_major> b;
                    wmma::load_matrix_sync(b, Bb + (wn * 64 + j * 16) * LDA + kk * 8, LDA);
                    #pragma unroll
                    for (int t = 0; t < b.num_elements; ++t)
                        b.x[t] = wmma::__float_to_tf32(b.x[t]);
                    #pragma unroll
                    for (int i = 0; i < 2; ++i)
                        wmma::mma_sync(c[i][j], a[i], b, c[i][j]);
                } else {
                    wmma::fragment<wmma::matrix_b, 16, 16, 8, wmma::precision::tf32, wmma::row_major> b;
                    wmma::load_matrix_sync(b, Bb + (kk * 8) * LDBN + (wn * 64 + j * 16), LDBN);
                    #pragma unroll
                    for (int t = 0; t < b.num_elements; ++t)
                        b.x[t] = wmma::__float_to_tf32(b.x[t]);
                    #pragma unroll
                    for (int i = 0; i < 2; ++i)
                        wmma::mma_sync(c[i][j], a[i], b, c[i][j]);
                }
            }
        }
        __syncthreads();
    }

    #pragma unroll
    for (int i = 0; i < 2; ++i)
        #pragma unroll
        for (int j = 0; j < 4; ++j)
            wmma::store_matrix_sync(
                C + (size_t)(m0 + wm * 32 + i * 16) * ldc + (n0 + wn * 64 + j * 16),
                c[i][j], ldc, wmma::mem_row_major);
}

// ---------------------------------------------------------------------------
// QKV scatter: g_fused [4096,6144] + bias -> g_q(*INV_NORM)/g_k/g_v
// ---------------------------------------------------------------------------
__global__ __launch_bounds__(256)
void qkv_scatter(const float* __restrict__ bias)
{
    const size_t i4 = ((size_t)blockIdx.x * 256 + threadIdx.x) * 4;
    const int m = (int)(i4 / (3 * Hc));
    const int n = (int)(i4 % (3 * Hc));
    float4 v  = *(const float4*)&g_fused[i4];
    float4 bb = *(const float4*)&bias[n];
    v.x += bb.x; v.y += bb.y; v.z += bb.z; v.w += bb.w;

    const int nh = n / (3 * HDc);
    const int r  = n - nh * 3 * HDc;
    const int t  = r / HDc;
    const int d  = r - t * HDc;
    const int b  = m / Sc;
    const int s  = m - b * Sc;
    const size_t off = ((size_t)(b * NHc + nh) * Sc + s) * HDc + d;

    if (t == 0) {
        v.x *= INV_NORM; v.y *= INV_NORM; v.z *= INV_NORM; v.w *= INV_NORM;
        *(float4*)&g_q[off] = v;
    } else if (t == 1) {
        *(float4*)&g_k[off] = v;
    } else {
        *(float4*)&g_v[off] = v;
    }
}

// ---------------------------------------------------------------------------
// Fused alibi + mask + softmax over g_p rows (2048 wide).
// ---------------------------------------------------------------------------
__global__ __launch_bounds__(256)
void softmax_kernel(const float* __restrict__ alibi, const int* __restrict__ mask)
{
    const size_t row = blockIdx.x;
    const int z = (int)(row / Sc);
    const int m = (int)(row % Sc);
    float* pr = g_p + row * (size_t)Sc;
    const float* al = alibi + (size_t)z * Sc;
    const int* mr = mask + (size_t)m * Sc;

    const int t = threadIdx.x;
    const int lane = t & 31, warp = t >> 5;
    __shared__ float red[8];

    float v[8];
    float mx = -INFINITY;
    #pragma unroll
    for (int i = 0; i < 8; ++i) {
        const int col = i * 256 + t;
        float s = pr[col] + al[col];
        if (mr[col] != 0) s = NEGF;
        v[i] = s;
        mx = fmaxf(mx, s);
    }
    #pragma unroll
    for (int o = 16; o > 0; o >>= 1) mx = fmaxf(mx, __shfl_xor_sync(0xffffffffu, mx, o));
    if (lane == 0) red[warp] = mx;
    __syncthreads();
    mx = red[0];
    #pragma unroll
    for (int w = 1; w < 8; ++w) mx = fmaxf(mx, red[w]);
    __syncthreads();

    float sum = 0.f;
    #pragma unroll
    for (int i = 0; i < 8; ++i) { v[i] = expf(v[i] - mx); sum += v[i]; }
    #pragma unroll
    for (int o = 16; o > 0; o >>= 1) sum += __shfl_xor_sync(0xffffffffu, sum, o);
    if (lane == 0) red[warp] = sum;
    __syncthreads();
    float tot = red[0];
    #pragma unroll
    for (int w = 1; w < 8; ++w) tot += red[w];
    const float inv = 1.0f / tot;
    #pragma unroll
    for (int i = 0; i < 8; ++i) pr[i * 256 + t] = v[i] * inv;
}

// ---------------------------------------------------------------------------
// Dense epilogue fixup: out += b_dense[n] + residual
// ---------------------------------------------------------------------------
__global__ __launch_bounds__(256)
void dense_epilogue(float* __restrict__ out, const float* __restrict__ bias,
                    const float* __restrict__ residual)
{
    const size_t i4 = ((size_t)blockIdx.x * 256 + threadIdx.x) * 4;
    const int n = (int)(i4 % Hc);
    float4 v  = *(float4*)&out[i4];
    float4 bb = *(const float4*)&bias[n];
    float4 rr = *(const float4*)&residual[i4];
    v.x += bb.x + rr.x; v.y += bb.y + rr.y; v.z += bb.z + rr.z; v.w += bb.w + rr.w;
    *(float4*)&out[i4] = v;
}

// ---------------------------------------------------------------------------
// Inputs (metadata order): hidden_states, residual, alibi, attention_mask(int32),
//                          w_qkv, b_qkv, w_dense, b_dense
// ---------------------------------------------------------------------------
extern "C" void kernel_launch(void* const* d_in, const int* in_sizes, int n_in,
                              void* d_out, int out_size)
{
    (void)in_sizes; (void)n_in; (void)out_size;
    const float* hs       = (const float*)d_in[0];
    const float* residual = (const float*)d_in[1];
    const float* alibi    = (const float*)d_in[2];
    const int*   mask     = (const int*)d_in[3];      // bool upcast to int32 by harness
    const float* w_qkv    = (const float*)d_in[4];
    const float* b_qkv    = (const float*)d_in[5];
    const float* w_dense  = (const float*)d_in[6];
    const float* b_dense  = (const float*)d_in[7];
    float*       out      = (float*)d_out;

    static bool attr_done = false;
    if (!attr_done) {
        cudaFuncSetAttribute(gemm_tf32<0>, cudaFuncAttributeMaxDynamicSharedMemorySize, (int)SMEM_BYTES);
        cudaFuncSetAttribute(gemm_tf32<1>, cudaFuncAttributeMaxDynamicSharedMemorySize, (int)SMEM_BYTES);
        cudaFuncSetAttribute(gemm_tf32<2>, cudaFuncAttributeMaxDynamicSharedMemorySize, (int)SMEM_BYTES);
        cudaFuncSetAttribute(gemm_tf32<3>, cudaFuncAttributeMaxDynamicSharedMemorySize, (int)SMEM_BYTES);
        attr_done = true;
    }

    const dim3 blk(256);

    // 1) raw QKV GEMM: g_fused = hs @ w_qkv^T   [4096, 6144]
    gemm_tf32<0><<<dim3((3 * Hc) / BN, (Bc * Sc) / BM, 1), blk, SMEM_BYTES>>>(hs, w_qkv, nullptr);

    // 2) scatter + bias + q-prescale
    qkv_scatter<<<(unsigned)((size_t)Bc * Sc * 3 * Hc / 4 / 256), blk>>>(b_qkv);

    // 3) raw scores: g_p[z] = q' @ k^T
    gemm_tf32<1><<<dim3(Sc / BN, Sc / BM, BHc), blk, SMEM_BYTES>>>(nullptr, nullptr, nullptr);

    // 4) alibi + mask + softmax
    softmax_kernel<<<BHc * Sc, 256>>>(alibi, mask);

    // 5) ctx: g_ctx = probs @ v   (scattered into [B,S,H])
    gemm_tf32<2><<<dim3(HDc / BN, Sc / BM, BHc), blk, SMEM_BYTES>>>(nullptr, nullptr, nullptr);

    // 6) out = ctx @ w_dense^T
    gemm_tf32<3><<<dim3(Hc / BN, (Bc * Sc) / BM, 1), blk, SMEM_BYTES>>>(nullptr, w_dense, out);

    // 7) out += b_dense + residual
    dense_epilogue<<<(unsigned)((size_t)Bc * Sc * Hc / 4 / 256), blk>>>(out, b_dense, residual);
}

// round 6
// speedup vs baseline: 1.7336x; 1.0000x over previous
#include <cuda_runtime.h>
#include <mma.h>
#include <stdint.h>
#include <math.h>

using namespace nvcuda;

// Problem constants (B=2, S=2048, H=2048, NH=16, HD=128)
namespace {
constexpr int Bc  = 2;
constexpr int Sc  = 2048;
constexpr int Hc  = 2048;
constexpr int NHc = 16;
constexpr int HDc = 128;
constexpr int BHc = Bc * NHc;                       // 32 batch-heads
constexpr float INV_NORM = 0.08838834764831845f;    // 1/sqrt(128)
constexpr float NEGF = -3.402823466385288598e38f;   // finfo(f32).min

constexpr int BM = 128, BN = 128, BK = 32;
constexpr int PAD  = 8;
constexpr int LDA  = BK + PAD;                      // 40
constexpr int LDBN = BN + PAD;                      // 136 (NN tiles)
constexpr int ASZ  = BM * LDA;                      // 5120 floats per stage
constexpr int BSZ  = 5120;                          // max(BN*LDA=5120, BK*LDBN=4352)
constexpr size_t SMEM_BYTES = (size_t)(2 * ASZ + 2 * BSZ) * 4;   // 81920
}

// Scratch (device globals: allocation-free per harness rules)
__device__ __align__(16) float g_q[(size_t)BHc * Sc * HDc];       // pre-scaled by 1/sqrt(HD)
__device__ __align__(16) float g_k[(size_t)BHc * Sc * HDc];
__device__ __align__(16) float g_v[(size_t)BHc * Sc * HDc];
__device__ __align__(16) float g_ctx[(size_t)Bc * Sc * Hc];       // [B,S,H]
__device__ __align__(16) float g_fused[(size_t)Bc * Sc * 3 * Hc]; // raw QKV out [4096,6144]
__device__ __align__(16) float g_p[(size_t)BHc * Sc * Sc];        // scores/probs (512 MB)

__device__ __forceinline__ void cp_async16(float* sptr, const float* gptr) {
    uint32_t saddr = (uint32_t)__cvta_generic_to_shared(sptr);
    asm volatile("cp.async.cg.shared.global [%0], [%1], 16;\n" :: "r"(saddr), "l"(gptr));
}
__device__ __forceinline__ void cp_commit() { asm volatile("cp.async.commit_group;\n"); }
template<int N>
__device__ __forceinline__ void cp_wait() { asm volatile("cp.async.wait_group %0;\n" :: "n"(N)); }

// ---------------------------------------------------------------------------
// tf32 wmma GEMM, cp.async double-buffered. C = A @ op(B).
//  MODE 0: g_fused = hs @ w_qkv^T      (NT)  M=4096 N=6144 K=2048
//  MODE 1: g_p[z]  = q[z] @ k[z]^T     (NT)  M=N=2048 K=128, batched z
//  MODE 2: g_ctx   = probs[z] @ v[z]   (NN)  M=2048 N=128 K=2048, batched
//  MODE 3: out     = g_ctx @ w_dense^T (NT)  M=4096 N=2048 K=2048
// NT B-tiles stored untransposed [BN][BK] -> wmma col_major fragments.
// 8 warps (4x2), warp tile 32x64, m16n16k8.
// ---------------------------------------------------------------------------
template<int MODE>
__global__ __launch_bounds__(256, 2)
void gemm_tf32(const float* __restrict__ Ag, const float* __restrict__ Bg,
               float* __restrict__ Cg)
{
    constexpr bool NT = (MODE != 2);
    const int z = blockIdx.z;

    const float* A;  const float* Bm;  float* C;
    int lda, ldb, ldc, K;
    if constexpr (MODE == 0) {
        A = Ag;  lda = Hc;  Bm = Bg;  ldb = Hc;  K = Hc;
        C = g_fused;  ldc = 3 * Hc;
    } else if constexpr (MODE == 1) {
        A = g_q + (size_t)z * Sc * HDc;  lda = HDc;
        Bm = g_k + (size_t)z * Sc * HDc; ldb = HDc;  K = HDc;
        C = g_p + (size_t)z * Sc * Sc;   ldc = Sc;
    } else if constexpr (MODE == 2) {
        A = g_p + (size_t)z * Sc * Sc;   lda = Sc;
        Bm = g_v + (size_t)z * Sc * HDc; ldb = HDc;  K = Sc;
        const int b = z / NHc, nh = z - b * NHc;
        C = g_ctx + (size_t)(b * Sc) * Hc + nh * HDc;  ldc = Hc;
    } else {
        A = g_ctx;  lda = Hc;  Bm = Bg;  ldb = Hc;  K = Hc;
        C = Cg;  ldc = Hc;
    }

    extern __shared__ float smem[];
    float* As = smem;                 // [2][BM][LDA]
    float* Bs = smem + 2 * ASZ;       // [2][BN][LDA] (NT) or [2][BK][LDBN] (NN)

    const int tid  = threadIdx.x;
    const int warp = tid >> 5;
    const int wm   = warp >> 1;       // 0..3 -> 32-row slice
    const int wn   = warp & 1;        // 0..1 -> 64-col slice
    const int m0   = blockIdx.y * BM;
    const int n0   = blockIdx.x * BN;

    // tile loaders: 1024 x 16B chunks each, 4 per thread
    auto load_A = [&](int st, int k0) {
        #pragma unroll
        for (int c = 0; c < 4; ++c) {
            const int idx = tid + c * 256;
            const int row = idx >> 3, col = (idx & 7) * 4;
            cp_async16(&As[st * ASZ + row * LDA + col],
                       A + (size_t)(m0 + row) * lda + (k0 + col));
        }
    };
    auto load_B = [&](int st, int k0) {
        if constexpr (NT) {
            #pragma unroll
            for (int c = 0; c < 4; ++c) {
                const int idx = tid + c * 256;
                const int row = idx >> 3, col = (idx & 7) * 4;   // row=n, col=k
                cp_async16(&Bs[st * BSZ + row * LDA + col],
                           Bm + (size_t)(n0 + row) * ldb + (k0 + col));
            }
        } else {
            #pragma unroll
            for (int c = 0; c < 4; ++c) {
                const int idx = tid + c * 256;
                const int k = idx >> 5, n4 = (idx & 31) * 4;
                cp_async16(&Bs[st * BSZ + k * LDBN + n4],
                           Bm + (size_t)(k0 + k) * ldb + (n0 + n4));
            }
        }
    };

    wmma::fragment<wmma::accumulator, 16, 16, 8, float> c[2][4];
    #pragma unroll
    for (int i = 0; i < 2; ++i)
        #pragma unroll
        for (int j = 0; j < 4; ++j) wmma::fill_fragment(c[i][j], 0.0f);

    load_A(0, 0); load_B(0, 0); cp_commit();

    for (int k0 = 0; k0 < K; k0 += BK) {
        const int cur = (k0 / BK) & 1;
        if (k0 + BK < K) {
            load_A(cur ^ 1, k0 + BK); load_B(cur ^ 1, k0 + BK);
            cp_commit();
            cp_wait<1>();
        } else {
            cp_wait<0>();
        }
        __syncthreads();

        const float* Ab = &As[cur * ASZ];
        const float* Bb = &Bs[cur * BSZ];
        #pragma unroll
        for (int kk = 0; kk < BK / 8; ++kk) {
            wmma::fragment<wmma::matrix_a, 16, 16, 8, wmma::precision::tf32, wmma::row_major> a[2];
            #pragma unroll
            for (int i = 0; i < 2; ++i) {
                wmma::load_matrix_sync(a[i], Ab + (wm * 32 + i * 16) * LDA + kk * 8, LDA);
                #pragma unroll
                for (int t = 0; t < a[i].num_elements; ++t)
                    a[i].x[t] = wmma::__float_to_tf32(a[i].x[t]);
            }
            #pragma unroll
            for (int j = 0; j < 4; ++j) {
                if constexpr (NT) {
                    wmma::fragment<wmma::matrix_b, 16, 16, 8, wmma::precision::tf32, wmma::col_major> b;
                    wmma::load_matrix_sync(b, Bb + (wn * 64 + j * 16) * LDA + kk * 8, LDA);
                    #pragma unroll
                    for (int t = 0; t < b.num_elements; ++t)
                        b.x[t] = wmma::__float_to_tf32(b.x[t]);
                    #pragma unroll
                    for (int i = 0; i < 2; ++i)
                        wmma::mma_sync(c[i][j], a[i], b, c[i][j]);
                } else {
                    wmma::fragment<wmma::matrix_b, 16, 16, 8, wmma::precision::tf32, wmma::row_major> b;
                    wmma::load_matrix_sync(b, Bb + (kk * 8) * LDBN + (wn * 64 + j * 16), LDBN);
                    #pragma unroll
                    for (int t = 0; t < b.num_elements; ++t)
                        b.x[t] = wmma::__float_to_tf32(b.x[t]);
                    #pragma unroll
                    for (int i = 0; i < 2; ++i)
                        wmma::mma_sync(c[i][j], a[i], b, c[i][j]);
                }
            }
        }
        __syncthreads();
    }

    #pragma unroll
    for (int i = 0; i < 2; ++i)
        #pragma unroll
        for (int j = 0; j < 4; ++j)
            wmma::store_matrix_sync(
                C + (size_t)(m0 + wm * 32 + i * 16) * ldc + (n0 + wn * 64 + j * 16),
                c[i][j], ldc, wmma::mem_row_major);
}

// ---------------------------------------------------------------------------
// QKV scatter: g_fused [4096,6144] + bias -> g_q(*INV_NORM)/g_k/g_v
// ---------------------------------------------------------------------------
__global__ __launch_bounds__(256)
void qkv_scatter(const float* __restrict__ bias)
{
    const size_t i4 = ((size_t)blockIdx.x * 256 + threadIdx.x) * 4;
    const int m = (int)(i4 / (3 * Hc));
    const int n = (int)(i4 % (3 * Hc));
    float4 v  = *(const float4*)&g_fused[i4];
    float4 bb = *(const float4*)&bias[n];
    v.x += bb.x; v.y += bb.y; v.z += bb.z; v.w += bb.w;

    const int nh = n / (3 * HDc);
    const int r  = n - nh * 3 * HDc;
    const int t  = r / HDc;
    const int d  = r - t * HDc;
    const int b  = m / Sc;
    const int s  = m - b * Sc;
    const size_t off = ((size_t)(b * NHc + nh) * Sc + s) * HDc + d;

    if (t == 0) {
        v.x *= INV_NORM; v.y *= INV_NORM; v.z *= INV_NORM; v.w *= INV_NORM;
        *(float4*)&g_q[off] = v;
    } else if (t == 1) {
        *(float4*)&g_k[off] = v;
    } else {
        *(float4*)&g_v[off] = v;
    }
}

// ---------------------------------------------------------------------------
// Fused alibi + mask + softmax over g_p rows (2048 wide).
// ---------------------------------------------------------------------------
__global__ __launch_bounds__(256)
void softmax_kernel(const float* __restrict__ alibi, const int* __restrict__ mask)
{
    const size_t row = blockIdx.x;
    const int z = (int)(row / Sc);
    const int m = (int)(row % Sc);
    float* pr = g_p + row * (size_t)Sc;
    const float* al = alibi + (size_t)z * Sc;
    const int* mr = mask + (size_t)m * Sc;

    const int t = threadIdx.x;
    const int lane = t & 31, warp = t >> 5;
    __shared__ float red[8];

    float v[8];
    float mx = -INFINITY;
    #pragma unroll
    for (int i = 0; i < 8; ++i) {
        const int col = i * 256 + t;
        float s = pr[col] + al[col];
        if (mr[col] != 0) s = NEGF;
        v[i] = s;
        mx = fmaxf(mx, s);
    }
    #pragma unroll
    for (int o = 16; o > 0; o >>= 1) mx = fmaxf(mx, __shfl_xor_sync(0xffffffffu, mx, o));
    if (lane == 0) red[warp] = mx;
    __syncthreads();
    mx = red[0];
    #pragma unroll
    for (int w = 1; w < 8; ++w) mx = fmaxf(mx, red[w]);
    __syncthreads();

    float sum = 0.f;
    #pragma unroll
    for (int i = 0; i < 8; ++i) { v[i] = expf(v[i] - mx); sum += v[i]; }
    #pragma unroll
    for (int o = 16; o > 0; o >>= 1) sum += __shfl_xor_sync(0xffffffffu, sum, o);
    if (lane == 0) red[warp] = sum;
    __syncthreads();
    float tot = red[0];
    #pragma unroll
    for (int w = 1; w < 8; ++w) tot += red[w];
    const float inv = 1.0f / tot;
    #pragma unroll
    for (int i = 0; i < 8; ++i) pr[i * 256 + t] = v[i] * inv;
}

// ---------------------------------------------------------------------------
// Dense epilogue fixup: out += b_dense[n] + residual
// ---------------------------------------------------------------------------
__global__ __launch_bounds__(256)
void dense_epilogue(float* __restrict__ out, const float* __restrict__ bias,
                    const float* __restrict__ residual)
{
    const size_t i4 = ((size_t)blockIdx.x * 256 + threadIdx.x) * 4;
    const int n = (int)(i4 % Hc);
    float4 v  = *(float4*)&out[i4];
    float4 bb = *(const float4*)&bias[n];
    float4 rr = *(const float4*)&residual[i4];
    v.x += bb.x + rr.x; v.y += bb.y + rr.y; v.z += bb.z + rr.z; v.w += bb.w + rr.w;
    *(float4*)&out[i4] = v;
}

// ---------------------------------------------------------------------------
// Inputs (metadata order): hidden_states, residual, alibi, attention_mask(int32),
//                          w_qkv, b_qkv, w_dense, b_dense
// ---------------------------------------------------------------------------
extern "C" void kernel_launch(void* const* d_in, const int* in_sizes, int n_in,
                              void* d_out, int out_size)
{
    (void)in_sizes; (void)n_in; (void)out_size;
    const float* hs       = (const float*)d_in[0];
    const float* residual = (const float*)d_in[1];
    const float* alibi    = (const float*)d_in[2];
    const int*   mask     = (const int*)d_in[3];      // bool upcast to int32 by harness
    const float* w_qkv    = (const float*)d_in[4];
    const float* b_qkv    = (const float*)d_in[5];
    const float* w_dense  = (const float*)d_in[6];
    const float* b_dense  = (const float*)d_in[7];
    float*       out      = (float*)d_out;

    static bool attr_done = false;
    if (!attr_done) {
        cudaFuncSetAttribute(gemm_tf32<0>, cudaFuncAttributeMaxDynamicSharedMemorySize, (int)SMEM_BYTES);
        cudaFuncSetAttribute(gemm_tf32<1>, cudaFuncAttributeMaxDynamicSharedMemorySize, (int)SMEM_BYTES);
        cudaFuncSetAttribute(gemm_tf32<2>, cudaFuncAttributeMaxDynamicSharedMemorySize, (int)SMEM_BYTES);
        cudaFuncSetAttribute(gemm_tf32<3>, cudaFuncAttributeMaxDynamicSharedMemorySize, (int)SMEM_BYTES);
        attr_done = true;
    }

    const dim3 blk(256);

    // 1) raw QKV GEMM: g_fused = hs @ w_qkv^T   [4096, 6144]
    gemm_tf32<0><<<dim3((3 * Hc) / BN, (Bc * Sc) / BM, 1), blk, SMEM_BYTES>>>(hs, w_qkv, nullptr);

    // 2) scatter + bias + q-prescale
    qkv_scatter<<<(unsigned)((size_t)Bc * Sc * 3 * Hc / 4 / 256), blk>>>(b_qkv);

    // 3) raw scores: g_p[z] = q' @ k^T
    gemm_tf32<1><<<dim3(Sc / BN, Sc / BM, BHc), blk, SMEM_BYTES>>>(nullptr, nullptr, nullptr);

    // 4) alibi + mask + softmax
    softmax_kernel<<<BHc * Sc, 256>>>(alibi, mask);

    // 5) ctx: g_ctx = probs @ v   (scattered into [B,S,H])
    gemm_tf32<2><<<dim3(HDc / BN, Sc / BM, BHc), blk, SMEM_BYTES>>>(nullptr, nullptr, nullptr);

    // 6) out = ctx @ w_dense^T
    gemm_tf32<3><<<dim3(Hc / BN, (Bc * Sc) / BM, 1), blk, SMEM_BYTES>>>(nullptr, w_dense, out);

    // 7) out += b_dense + residual
    dense_epilogue<<<(unsigned)((size_t)Bc * Sc * Hc / 4 / 256), blk>>>(out, b_dense, residual);
}